// round 2
// baseline (speedup 1.0000x reference)
#include <cuda_runtime.h>
#include <math.h>

#define T_SEQ 8192
#define EMB   512
#define HID   2048
#define NC    256
#define R4    8192      // 4*HID stacked gate rows (f,i,c,o)
#define WCOLS 2560      // EMB+HID
#define NB    128       // persistent CTAs (<=148 SMs -> all resident)
#define HPB   16        // hidden units per CTA (128*16 = 2048)

// ---------------- scratch (static device allocations are allowed) -----------
__device__ float g_X[(size_t)T_SEQ * EMB];          // 16 MB  gathered embeddings
__device__ float g_Gx[(size_t)T_SEQ * R4];          // 256 MB precomputed W_x@x_t + b
__device__ float g_Hall[(size_t)T_SEQ * HID];       // 64 MB  all hidden states
__device__ float g_h[2][HID];                       // double-buffered h
__device__ unsigned g_barcnt = 0;
__device__ unsigned g_sense  = 0;

// ---------------- grid barrier (sense-reversal, phases unique per launch) ---
__device__ __forceinline__ void gridbar(unsigned phase) {
    __syncthreads();
    if (threadIdx.x == 0) {
        __threadfence();
        unsigned a = atomicAdd(&g_barcnt, 1u);
        if (a == NB - 1u) {
            atomicExch(&g_barcnt, 0u);
            __threadfence();
            atomicExch(&g_sense, phase);
        } else {
            unsigned s;
            do {
                asm volatile("ld.acquire.gpu.u32 %0, [%1];" : "=r"(s) : "l"(&g_sense) : "memory");
            } while (s != phase);
        }
        __threadfence();
    }
    __syncthreads();
}

// ---------------- phase 0: gather embeddings --------------------------------
__global__ void gather_kernel(const int* __restrict__ seq,
                              const float* __restrict__ emb) {
    int t = blockIdx.x;
    int c = seq[t];
    for (int e = threadIdx.x; e < EMB; e += blockDim.x)
        g_X[(size_t)t * EMB + e] = emb[(size_t)c * EMB + e];
}

// ---------------- phase 1: Gx[t][r] = W_x @ x_t + b  (tiled SGEMM) ----------
__global__ void __launch_bounds__(256) gx_gemm(
    const float* __restrict__ Wf, const float* __restrict__ Wi,
    const float* __restrict__ Wc, const float* __restrict__ Wo,
    const float* __restrict__ bf, const float* __restrict__ bi,
    const float* __restrict__ bc, const float* __restrict__ bo) {
    const int r0 = blockIdx.x * 64;   // gate-row tile
    const int t0 = blockIdx.y * 64;   // time tile
    const int gate = r0 >> 11;
    const int j0 = r0 & (HID - 1);
    const float* W    = gate == 0 ? Wf : gate == 1 ? Wi : gate == 2 ? Wc : Wo;
    const float* bias = gate == 0 ? bf : gate == 1 ? bi : gate == 2 ? bc : bo;

    __shared__ float As[16][64];
    __shared__ float Bs[16][64];
    const int tid = threadIdx.x;
    const int tx = tid & 15, ty = tid >> 4;

    float acc[4][4];
#pragma unroll
    for (int i = 0; i < 4; i++)
#pragma unroll
        for (int j = 0; j < 4; j++) acc[i][j] = 0.f;

    for (int kk = 0; kk < EMB; kk += 16) {
#pragma unroll
        for (int l = tid; l < 1024; l += 256) {
            int k = l & 15, i = l >> 4;
            As[k][i] = g_X[(size_t)(t0 + i) * EMB + kk + k];
            Bs[k][i] = W[(size_t)(j0 + i) * WCOLS + kk + k];
        }
        __syncthreads();
#pragma unroll
        for (int k = 0; k < 16; k++) {
            float a[4], bb[4];
#pragma unroll
            for (int i = 0; i < 4; i++) a[i]  = As[k][ty * 4 + i];
#pragma unroll
            for (int j = 0; j < 4; j++) bb[j] = Bs[k][tx * 4 + j];
#pragma unroll
            for (int i = 0; i < 4; i++)
#pragma unroll
                for (int j = 0; j < 4; j++) acc[i][j] += a[i] * bb[j];
        }
        __syncthreads();
    }
#pragma unroll
    for (int i = 0; i < 4; i++)
#pragma unroll
        for (int j = 0; j < 4; j++)
            g_Gx[(size_t)(t0 + ty * 4 + i) * R4 + r0 + tx * 4 + j] =
                acc[i][j] + bias[j0 + tx * 4 + j];
}

// ---------------- phase 2: persistent sequential LSTM recurrence ------------
__global__ void __launch_bounds__(256, 1) lstm_rec(
    const float* __restrict__ Wf, const float* __restrict__ Wi,
    const float* __restrict__ Wc, const float* __restrict__ Wo,
    float* __restrict__ out) {
    const int b = blockIdx.x;
    const int tid = threadIdx.x;
    const int lane = tid & 31, w = tid >> 5;

    __shared__ float sh[HID];
    __shared__ float gsum[64];
    __shared__ float gxs[64];

    // 8 gate rows per warp: lr = w*8+i; gate = lr>>4, jj = lr&15
    const float4* wrow[8];
#pragma unroll
    for (int i = 0; i < 8; i++) {
        int lr = w * 8 + i;
        int gate = lr >> 4, jj = lr & 15;
        const float* W = gate == 0 ? Wf : gate == 1 ? Wi : gate == 2 ? Wc : Wo;
        wrow[i] = (const float4*)(W + (size_t)(b * HPB + jj) * WCOLS + EMB);
    }

    float c_reg = 0.f, h_last = 0.f;
    if (tid < HPB) g_h[0][b * HPB + tid] = 0.f;
    if (tid == 0) __threadfence();
    gridbar(1u);

    for (int t = 0; t < T_SEQ; t++) {
        const int cur = t & 1;
        // stage precomputed input-gate contributions for this CTA's 64 rows
        if (tid < 64) {
            int gate = tid >> 4, jj = tid & 15;
            gxs[tid] = g_Gx[(size_t)t * R4 + gate * HID + b * HPB + jj];
        }
        // stage h into SMEM
        {
            const float4* hsrc = (const float4*)g_h[cur];
            float4* shd = (float4*)sh;
            shd[tid]       = hsrc[tid];
            shd[tid + 256] = hsrc[tid + 256];
        }
        __syncthreads();

        float acc[8];
#pragma unroll
        for (int i = 0; i < 8; i++) acc[i] = 0.f;
        const float4* sh4 = (const float4*)sh;
#pragma unroll 4
        for (int m = 0; m < 16; m++) {
            float4 hv = sh4[lane + 32 * m];
#pragma unroll
            for (int i = 0; i < 8; i++) {
                float4 wv = wrow[i][lane + 32 * m];
                acc[i] += wv.x * hv.x + wv.y * hv.y + wv.z * hv.z + wv.w * hv.w;
            }
        }
#pragma unroll
        for (int i = 0; i < 8; i++) {
            float v = acc[i];
#pragma unroll
            for (int s = 16; s; s >>= 1) v += __shfl_xor_sync(0xffffffffu, v, s);
            if (lane == 0) gsum[w * 8 + i] = v;
        }
        __syncthreads();

        if (tid < HPB) {
            float gf = gsum[tid]      + gxs[tid];
            float gi = gsum[16 + tid] + gxs[16 + tid];
            float gc = gsum[32 + tid] + gxs[32 + tid];
            float go = gsum[48 + tid] + gxs[48 + tid];
            float f  = 1.f / (1.f + expf(-gf));
            float ii = 1.f / (1.f + expf(-gi));
            float ct = tanhf(gc);
            float o  = 1.f / (1.f + expf(-go));
            c_reg = f * c_reg + ii * ct;
            float hn = o * tanhf(c_reg);
            h_last = hn;
            g_h[cur ^ 1][b * HPB + tid] = hn;
            g_Hall[(size_t)t * HID + b * HPB + tid] = hn;
            __threadfence();
        }
        gridbar((unsigned)(t + 2));
    }

    if (tid < HPB) {
        out[(size_t)T_SEQ * NC + b * HPB + tid]       = h_last;   // final h
        out[(size_t)T_SEQ * NC + HID + b * HPB + tid] = c_reg;    // final c
    }
}

// ---------------- phase 3: Y = Hall @ W_y^T + b_y ---------------------------
__global__ void __launch_bounds__(256) y_gemm(
    const float* __restrict__ Wy, const float* __restrict__ by,
    float* __restrict__ out) {
    const int n0 = blockIdx.x * 64;
    const int t0 = blockIdx.y * 64;
    __shared__ float As[16][64];
    __shared__ float Bs[16][64];
    const int tid = threadIdx.x;
    const int tx = tid & 15, ty = tid >> 4;

    float acc[4][4];
#pragma unroll
    for (int i = 0; i < 4; i++)
#pragma unroll
        for (int j = 0; j < 4; j++) acc[i][j] = 0.f;

    for (int kk = 0; kk < HID; kk += 16) {
#pragma unroll
        for (int l = tid; l < 1024; l += 256) {
            int k = l & 15, i = l >> 4;
            As[k][i] = g_Hall[(size_t)(t0 + i) * HID + kk + k];
            Bs[k][i] = Wy[(size_t)(n0 + i) * HID + kk + k];
        }
        __syncthreads();
#pragma unroll
        for (int k = 0; k < 16; k++) {
            float a[4], bb[4];
#pragma unroll
            for (int i = 0; i < 4; i++) a[i]  = As[k][ty * 4 + i];
#pragma unroll
            for (int j = 0; j < 4; j++) bb[j] = Bs[k][tx * 4 + j];
#pragma unroll
            for (int i = 0; i < 4; i++)
#pragma unroll
                for (int j = 0; j < 4; j++) acc[i][j] += a[i] * bb[j];
        }
        __syncthreads();
    }
#pragma unroll
    for (int i = 0; i < 4; i++)
#pragma unroll
        for (int j = 0; j < 4; j++)
            out[(size_t)(t0 + ty * 4 + i) * NC + n0 + tx * 4 + j] =
                acc[i][j] + by[n0 + tx * 4 + j];
}

// ---------------- launch ----------------------------------------------------
extern "C" void kernel_launch(void* const* d_in, const int* in_sizes, int n_in,
                              void* d_out, int out_size) {
    const int*   seq = (const int*)  d_in[0];
    const float* emb = (const float*)d_in[1];
    const float* Wf  = (const float*)d_in[2];
    const float* bf  = (const float*)d_in[3];
    const float* Wi  = (const float*)d_in[4];
    const float* bi  = (const float*)d_in[5];
    const float* Wo  = (const float*)d_in[6];
    const float* bo  = (const float*)d_in[7];
    const float* Wc  = (const float*)d_in[8];
    const float* bc  = (const float*)d_in[9];
    const float* Wy  = (const float*)d_in[10];
    const float* by  = (const float*)d_in[11];
    float* out = (float*)d_out;

    gather_kernel<<<T_SEQ, 128>>>(seq, emb);

    dim3 g1(R4 / 64, T_SEQ / 64);
    gx_gemm<<<g1, 256>>>(Wf, Wi, Wc, Wo, bf, bi, bc, bo);

    lstm_rec<<<NB, 256>>>(Wf, Wi, Wc, Wo, out);

    dim3 g2(NC / 64, T_SEQ / 64);
    y_gemm<<<g2, 256>>>(Wy, by, out);
}